// round 3
// baseline (speedup 1.0000x reference)
#include <cuda_runtime.h>
#include <cuda_bf16.h>
#include <cstdint>

// ===================== problem sizes =====================
#define SEQ   2048
#define HID   8192
#define NTOT  10240          // 8192 q + 1024 k + 1024 v
#define Q_ELEMS   ((size_t)64 * SEQ * 128)
#define KV_ELEMS  ((size_t)8  * SEQ * 128)

// ===================== scratch =====================
__device__ signed char g_A0[(size_t)SEQ * HID];
__device__ signed char g_A1[(size_t)SEQ * HID];
__device__ signed char g_B0[(size_t)NTOT * HID];
__device__ signed char g_B1[(size_t)NTOT * HID];
__device__ int g_maxbits[2];   // [0]=max|x| bits, [1]=max|w| bits

// ===================== scale / quantize kernels =====================
__global__ void init_max_kernel() {
    if (threadIdx.x < 2) g_maxbits[threadIdx.x] = 0;
}

__global__ void maxabs_kernel(const float* __restrict__ p, size_t n4, int slot) {
    float m = 0.f;
    for (size_t i = (size_t)blockIdx.x * blockDim.x + threadIdx.x;
         i < n4; i += (size_t)gridDim.x * blockDim.x) {
        float4 v = reinterpret_cast<const float4*>(p)[i];
        m = fmaxf(m, fmaxf(fmaxf(fabsf(v.x), fabsf(v.y)),
                           fmaxf(fabsf(v.z), fabsf(v.w))));
    }
    #pragma unroll
    for (int s = 16; s > 0; s >>= 1)
        m = fmaxf(m, __shfl_xor_sync(0xFFFFFFFFu, m, s));
    if ((threadIdx.x & 31) == 0)
        atomicMax(&g_maxbits[slot], __float_as_int(m));
}

__device__ __forceinline__ void quant2(float v, float inv,
                                       signed char& c0, signed char& c1) {
    float t = v * inv;                       // in [-127, 127]
    float a0 = rintf(t);
    float a1 = rintf((t - a0) * 256.0f);
    a1 = fminf(127.f, fmaxf(-127.f, a1));
    c0 = (signed char)(int)a0;
    c1 = (signed char)(int)a1;
}

__global__ void quant_x_kernel(const float* __restrict__ x) {
    float S = fmaxf(__int_as_float(g_maxbits[0]), 1e-30f);
    float inv = 127.0f / S;
    size_t n4 = (size_t)SEQ * HID / 4;
    for (size_t i = (size_t)blockIdx.x * blockDim.x + threadIdx.x;
         i < n4; i += (size_t)gridDim.x * blockDim.x) {
        float4 v = reinterpret_cast<const float4*>(x)[i];
        float f[4] = {v.x, v.y, v.z, v.w};
        signed char q0[4], q1[4];
        #pragma unroll
        for (int j = 0; j < 4; j++) quant2(f[j], inv, q0[j], q1[j]);
        reinterpret_cast<char4*>(g_A0)[i] = make_char4(q0[0], q0[1], q0[2], q0[3]);
        reinterpret_cast<char4*>(g_A1)[i] = make_char4(q1[0], q1[1], q1[2], q1[3]);
    }
}

// src: [HID rows][ncols] row-major fp32; writes B[n_off+n][k] = src[k][n] (int8 x2)
__global__ void transpose_quant_kernel(const float* __restrict__ src,
                                       int ncols, int n_off) {
    __shared__ float tile[32][33];
    float S = fmaxf(__int_as_float(g_maxbits[1]), 1e-30f);
    float inv = 127.0f / S;
    int c0b = blockIdx.x * 32;    // column (N) base
    int r0 = blockIdx.y * 32;     // row (K) base
    int tx = threadIdx.x, ty = threadIdx.y;
    #pragma unroll
    for (int i = 0; i < 32; i += 8)
        tile[ty + i][tx] = src[(size_t)(r0 + ty + i) * ncols + (c0b + tx)];
    __syncthreads();
    #pragma unroll
    for (int i = 0; i < 32; i += 8) {
        int n = n_off + c0b + ty + i;
        int k = r0 + tx;
        signed char q0, q1;
        quant2(tile[tx][ty + i], inv, q0, q1);
        g_B0[(size_t)n * HID + k] = q0;
        g_B1[(size_t)n * HID + k] = q1;
    }
}

// ===================== GEMM kernel =====================
#define GEMM_THREADS 256
#define STAGES       3
#define STAGE_BYTES  65536       // 4 tiles x 16KB (128 rows x 128B int8, SW128)
#define GEMM_SMEM    (STAGES * STAGE_BYTES + 1024)

#define LDSM4(r0, r1, r2, r3, addr) \
    asm volatile("ldmatrix.sync.aligned.m8n8.x4.shared.b16 {%0,%1,%2,%3}, [%4];" \
        : "=r"(r0), "=r"(r1), "=r"(r2), "=r"(r3) : "r"(addr))

#define IMMA(d, a, b0, b1) \
    asm volatile("mma.sync.aligned.m16n8k32.row.col.s32.s8.s8.s32 " \
        "{%0,%1,%2,%3},{%4,%5,%6,%7},{%8,%9},{%0,%1,%2,%3};" \
        : "+r"((d)[0]), "+r"((d)[1]), "+r"((d)[2]), "+r"((d)[3]) \
        : "r"((a)[0]), "r"((a)[1]), "r"((a)[2]), "r"((a)[3]), "r"(b0), "r"(b1))

__device__ __forceinline__ uint32_t smem_to_u32(const void* p) {
    uint32_t addr;
    asm("{ .reg .u64 t; cvta.to.shared.u64 t, %1; cvt.u32.u64 %0, t; }"
        : "=r"(addr) : "l"(p));
    return addr;
}

// cp.async one 128-row x 128-byte int8 tile into SW128-swizzled smem.
__device__ __forceinline__ void cp_tile(uint32_t sdst, const signed char* gsrc,
                                        int row0, int k0, int tid) {
    const char* g = (const char*)gsrc + (size_t)row0 * HID + k0;
    #pragma unroll
    for (int i = 0; i < 4; ++i) {
        int idx = i * 256 + tid;            // 0..1023
        int r = idx >> 3;                   // row 0..127
        int c = idx & 7;                    // 16B chunk 0..7
        uint32_t off = (uint32_t)(r * 128 + ((c ^ (r & 7)) * 16));
        const char* src = g + (size_t)r * HID + c * 16;
        asm volatile("cp.async.cg.shared.global [%0], [%1], 16;"
                     :: "r"(sdst + off), "l"(src) : "memory");
    }
}

__device__ __forceinline__ void load_stage(uint32_t sstage, int m0, int n0,
                                           int k0, int tid) {
    cp_tile(sstage,         g_A0, m0, k0, tid);
    cp_tile(sstage + 16384, g_A1, m0, k0, tid);
    cp_tile(sstage + 32768, g_B0, n0, k0, tid);
    cp_tile(sstage + 49152, g_B1, n0, k0, tid);
    asm volatile("cp.async.commit_group;" ::: "memory");
}

__global__ __launch_bounds__(GEMM_THREADS, 1)
void qkv_gemm_kernel(float* __restrict__ out) {
    extern __shared__ char smem_raw[];
    char* sm = (char*)(((uintptr_t)smem_raw + 1023) & ~(uintptr_t)1023);
    uint32_t sbase = smem_to_u32(sm);

    const int tid  = threadIdx.x;
    const int lane = tid & 31;
    const int wid  = tid >> 5;
    const int warp_m = wid & 3;    // 4 warps along M (32 rows each)
    const int warp_n = wid >> 2;   // 2 warps along N (64 cols each)

    const int m0 = (blockIdx.x & 15) << 7;        // M-fastest raster (L2 A reuse)
    const int n0 = (int)(blockIdx.x >> 4) << 7;

    int acc00[2][8][4];            // a0*b0
    int accX [2][8][4];            // a0*b1 + a1*b0   (both scale 2^-8)
    #pragma unroll
    for (int i = 0; i < 2; ++i)
        #pragma unroll
        for (int j = 0; j < 8; ++j)
            #pragma unroll
            for (int r = 0; r < 4; ++r) { acc00[i][j][r] = 0; accX[i][j][r] = 0; }

    // ldmatrix lane-role decomposition (same pattern as bf16 k16 case)
    const int a_row_l = lane & 15;
    const int a_chi   = lane >> 4;
    const int b_row_l = (lane & 7) + ((lane >> 4) & 1) * 8;
    const int b_chi   = (lane >> 3) & 1;

    // prologue: prefetch 2 stages
    load_stage(sbase + 0 * STAGE_BYTES, m0, n0, 0, tid);
    load_stage(sbase + 1 * STAGE_BYTES, m0, n0, 128, tid);

    const int NKT = HID / 128;   // 64
    for (int kt = 0; kt < NKT; ++kt) {
        if (kt + 2 < NKT)
            asm volatile("cp.async.wait_group 1;" ::: "memory");
        else
            asm volatile("cp.async.wait_group 0;" ::: "memory");
        __syncthreads();

        if (kt + 2 < NKT)
            load_stage(sbase + ((kt + 2) % STAGES) * STAGE_BYTES,
                       m0, n0, (kt + 2) * 128, tid);

        const uint32_t st  = sbase + (kt % STAGES) * STAGE_BYTES;
        const uint32_t sa0 = st;
        const uint32_t sa1 = st + 16384;
        const uint32_t sb0 = st + 32768;
        const uint32_t sb1 = st + 49152;

        #pragma unroll
        for (int ks = 0; ks < 4; ++ks) {          // 4 x k32 per 128-K stage
            // ---- A fragments, both slices, 2 m-frags ----
            uint32_t a0f[2][4], a1f[2][4];
            #pragma unroll
            for (int mf = 0; mf < 2; ++mf) {
                int row = warp_m * 32 + mf * 16 + a_row_l;
                int c   = 2 * ks + a_chi;
                uint32_t off = (uint32_t)(row * 128 + ((c ^ (row & 7)) * 16));
                LDSM4(a0f[mf][0], a0f[mf][1], a0f[mf][2], a0f[mf][3], sa0 + off);
                LDSM4(a1f[mf][0], a1f[mf][1], a1f[mf][2], a1f[mf][3], sa1 + off);
            }
            // ---- B fragments per 16-n group, then 12 IMMAs ----
            #pragma unroll
            for (int jp = 0; jp < 4; ++jp) {
                int row = warp_n * 64 + jp * 16 + b_row_l;
                int c   = 2 * ks + b_chi;
                uint32_t off = (uint32_t)(row * 128 + ((c ^ (row & 7)) * 16));
                uint32_t bb0[4], bb1[4];
                LDSM4(bb0[0], bb0[1], bb0[2], bb0[3], sb0 + off);
                LDSM4(bb1[0], bb1[1], bb1[2], bb1[3], sb1 + off);
                #pragma unroll
                for (int mf = 0; mf < 2; ++mf) {
                    IMMA(acc00[mf][2*jp],   a0f[mf], bb0[0], bb0[1]);
                    IMMA(accX [mf][2*jp],   a0f[mf], bb1[0], bb1[1]);
                    IMMA(accX [mf][2*jp],   a1f[mf], bb0[0], bb0[1]);
                    IMMA(acc00[mf][2*jp+1], a0f[mf], bb0[2], bb0[3]);
                    IMMA(accX [mf][2*jp+1], a0f[mf], bb1[2], bb1[3]);
                    IMMA(accX [mf][2*jp+1], a1f[mf], bb0[2], bb0[3]);
                }
            }
        }
    }

    // ---- epilogue: combine slices, scale, scatter to q/k/v head layout ----
    float SA = fmaxf(__int_as_float(g_maxbits[0]), 1e-30f);
    float SB = fmaxf(__int_as_float(g_maxbits[1]), 1e-30f);
    float sAB = (SA * SB) * (1.0f / (127.0f * 127.0f));

    size_t obase;
    if (n0 < 8192)
        obase = (size_t)(n0 >> 7) * ((size_t)SEQ * 128);
    else if (n0 < 9216)
        obase = Q_ELEMS + (size_t)((n0 - 8192) >> 7) * ((size_t)SEQ * 128);
    else
        obase = Q_ELEMS + KV_ELEMS + (size_t)((n0 - 9216) >> 7) * ((size_t)SEQ * 128);

    const int rbase = m0 + warp_m * 32 + (lane >> 2);
    const int cbase = warp_n * 64 + (lane & 3) * 2;
    #pragma unroll
    for (int mf = 0; mf < 2; ++mf) {
        #pragma unroll
        for (int j = 0; j < 8; ++j) {
            int m = rbase + mf * 16;
            int c = cbase + j * 8;
            float* p0 = out + obase + (size_t)m * 128 + c;
            p0[0] = ((float)acc00[mf][j][0] + (float)accX[mf][j][0] * 0.00390625f) * sAB;
            p0[1] = ((float)acc00[mf][j][1] + (float)accX[mf][j][1] * 0.00390625f) * sAB;
            float* p1 = p0 + 8 * 128;
            p1[0] = ((float)acc00[mf][j][2] + (float)accX[mf][j][2] * 0.00390625f) * sAB;
            p1[1] = ((float)acc00[mf][j][3] + (float)accX[mf][j][3] * 0.00390625f) * sAB;
        }
    }
}

// ===================== host launcher =====================
extern "C" void kernel_launch(void* const* d_in, const int* in_sizes, int n_in,
                              void* d_out, int out_size) {
    const float* x = nullptr; const float* wq = nullptr;
    const float* wk = nullptr; const float* wv = nullptr;
    for (int i = 0; i < n_in; ++i) {
        long long sz = in_sizes[i];
        const float* p = (const float*)d_in[i];
        if (sz == (long long)SEQ * HID)       { if (!x) x = p; }
        else if (sz == (long long)HID * 8192) { if (!wq) wq = p; }
        else if (sz == (long long)HID * 1024) { if (!wk) wk = p; else if (!wv) wv = p; }
    }
    float* out = (float*)d_out;

    cudaFuncSetAttribute(qkv_gemm_kernel,
                         cudaFuncAttributeMaxDynamicSharedMemorySize, GEMM_SMEM);

    // 0) per-tensor maxabs scales
    init_max_kernel<<<1, 32>>>();
    maxabs_kernel<<<1024, 256>>>(x,  (size_t)SEQ * HID / 4, 0);
    maxabs_kernel<<<1024, 256>>>(wq, (size_t)HID * 8192 / 4, 1);
    maxabs_kernel<<<1024, 256>>>(wk, (size_t)HID * 1024 / 4, 1);
    maxabs_kernel<<<1024, 256>>>(wv, (size_t)HID * 1024 / 4, 1);

    // 1) quantize activations into int8 slices
    quant_x_kernel<<<2048, 256>>>(x);

    // 2) transpose + quantize weights into B0/B1 [NTOT][HID]
    dim3 tb(32, 8);
    transpose_quant_kernel<<<dim3(8192 / 32, HID / 32), tb>>>(wq, 8192, 0);
    transpose_quant_kernel<<<dim3(1024 / 32, HID / 32), tb>>>(wk, 1024, 8192);
    transpose_quant_kernel<<<dim3(1024 / 32, HID / 32), tb>>>(wv, 1024, 9216);

    // 3) int8x2 Ozaki-split IMMA GEMM + fused q/k/v head scatter
    qkv_gemm_kernel<<<16 * 80, GEMM_THREADS, GEMM_SMEM>>>(out);
}

// round 4
// speedup vs baseline: 6.8627x; 6.8627x over previous
#include <cuda_runtime.h>
#include <cuda_fp16.h>
#include <cstdint>

// ===================== problem sizes =====================
#define SEQ   2048
#define HID   8192
#define NTOT  10240          // 8192 q + 1024 k + 1024 v
#define Q_ELEMS   ((size_t)64 * SEQ * 128)
#define KV_ELEMS  ((size_t)8  * SEQ * 128)

// ===================== scratch (fp16) =====================
__device__ unsigned short g_A[(size_t)SEQ * HID];
__device__ unsigned short g_B[(size_t)NTOT * HID];

// ===================== conversion kernels =====================
__global__ void convert_x_kernel(const float* __restrict__ x) {
    size_t n4 = (size_t)SEQ * HID / 4;
    for (size_t i = (size_t)blockIdx.x * blockDim.x + threadIdx.x;
         i < n4; i += (size_t)gridDim.x * blockDim.x) {
        float4 v = reinterpret_cast<const float4*>(x)[i];
        ushort4 h;
        h.x = __half_as_ushort(__float2half_rn(v.x));
        h.y = __half_as_ushort(__float2half_rn(v.y));
        h.z = __half_as_ushort(__float2half_rn(v.z));
        h.w = __half_as_ushort(__float2half_rn(v.w));
        reinterpret_cast<ushort4*>(g_A)[i] = h;
    }
}

// src: [HID rows][ncols] row-major fp32; writes B[n_off+n][k] = src[k][n] (fp16)
__global__ void transpose_half_kernel(const float* __restrict__ src,
                                      int ncols, int n_off) {
    __shared__ float tile[32][33];
    int c0b = blockIdx.x * 32;    // column (N) base
    int r0 = blockIdx.y * 32;     // row (K) base
    int tx = threadIdx.x, ty = threadIdx.y;
    #pragma unroll
    for (int i = 0; i < 32; i += 8)
        tile[ty + i][tx] = src[(size_t)(r0 + ty + i) * ncols + (c0b + tx)];
    __syncthreads();
    #pragma unroll
    for (int i = 0; i < 32; i += 8) {
        int n = n_off + c0b + ty + i;
        int k = r0 + tx;
        g_B[(size_t)n * HID + k] = __half_as_ushort(__float2half_rn(tile[tx][ty + i]));
    }
}

// ===================== GEMM kernel =====================
#define GEMM_THREADS 256
#define STAGES       4
#define STAGE_BYTES  32768       // 2 tiles x 16KB (128 rows x 128B fp16, SW128)
#define GEMM_SMEM    (STAGES * STAGE_BYTES + 1024)

#define LDSM4(r0, r1, r2, r3, addr) \
    asm volatile("ldmatrix.sync.aligned.m8n8.x4.shared.b16 {%0,%1,%2,%3}, [%4];" \
        : "=r"(r0), "=r"(r1), "=r"(r2), "=r"(r3) : "r"(addr))

#define MMA_F16(d, a, b0, b1) \
    asm volatile("mma.sync.aligned.m16n8k16.row.col.f32.f16.f16.f32 " \
        "{%0,%1,%2,%3},{%4,%5,%6,%7},{%8,%9},{%0,%1,%2,%3};" \
        : "+f"((d)[0]), "+f"((d)[1]), "+f"((d)[2]), "+f"((d)[3]) \
        : "r"((a)[0]), "r"((a)[1]), "r"((a)[2]), "r"((a)[3]), "r"(b0), "r"(b1))

__device__ __forceinline__ uint32_t smem_to_u32(const void* p) {
    uint32_t addr;
    asm("{ .reg .u64 t; cvta.to.shared.u64 t, %1; cvt.u32.u64 %0, t; }"
        : "=r"(addr) : "l"(p));
    return addr;
}

// cp.async one 128-row x 64-fp16 tile (128B rows) into SW128-swizzled smem.
__device__ __forceinline__ void cp_tile(uint32_t sdst, const unsigned short* gsrc,
                                        int row0, int k0, int tid) {
    const char* g = (const char*)(gsrc + (size_t)row0 * HID + k0);
    #pragma unroll
    for (int i = 0; i < 4; ++i) {
        int idx = i * 256 + tid;            // 0..1023
        int r = idx >> 3;                   // row 0..127
        int c = idx & 7;                    // 16B chunk 0..7
        uint32_t off = (uint32_t)(r * 128 + ((c ^ (r & 7)) * 16));
        const char* src = g + (size_t)r * (HID * 2) + c * 16;
        asm volatile("cp.async.cg.shared.global [%0], [%1], 16;"
                     :: "r"(sdst + off), "l"(src) : "memory");
    }
}

__device__ __forceinline__ void load_stage(uint32_t sstage, int m0, int n0,
                                           int k0, int tid) {
    cp_tile(sstage,         g_A, m0, k0, tid);
    cp_tile(sstage + 16384, g_B, n0, k0, tid);
    asm volatile("cp.async.commit_group;" ::: "memory");
}

__global__ __launch_bounds__(GEMM_THREADS, 1)
void qkv_gemm_kernel(float* __restrict__ out) {
    extern __shared__ char smem_raw[];
    char* sm = (char*)(((uintptr_t)smem_raw + 1023) & ~(uintptr_t)1023);
    uint32_t sbase = smem_to_u32(sm);

    const int tid  = threadIdx.x;
    const int lane = tid & 31;
    const int wid  = tid >> 5;
    const int warp_m = wid & 3;    // 4 warps along M (32 rows each)
    const int warp_n = wid >> 2;   // 2 warps along N (64 cols each)

    const int m0 = (blockIdx.x & 15) << 7;        // M-fastest raster (L2 A reuse)
    const int n0 = (int)(blockIdx.x >> 4) << 7;

    float acc[2][8][4];
    #pragma unroll
    for (int i = 0; i < 2; ++i)
        #pragma unroll
        for (int j = 0; j < 8; ++j)
            #pragma unroll
            for (int r = 0; r < 4; ++r) acc[i][j][r] = 0.f;

    // ldmatrix lane-role decomposition
    const int a_row_l = lane & 15;
    const int a_chi   = lane >> 4;
    const int b_row_l = (lane & 7) + ((lane >> 4) & 1) * 8;
    const int b_chi   = (lane >> 3) & 1;

    // prologue: prefetch STAGES-1 stages
    load_stage(sbase + 0 * STAGE_BYTES, m0, n0, 0,   tid);
    load_stage(sbase + 1 * STAGE_BYTES, m0, n0, 64,  tid);
    load_stage(sbase + 2 * STAGE_BYTES, m0, n0, 128, tid);

    const int NKT = HID / 64;   // 128
    for (int kt = 0; kt < NKT; ++kt) {
        if (kt + 3 < NKT)
            asm volatile("cp.async.wait_group 2;" ::: "memory");
        else
            asm volatile("cp.async.wait_group 0;" ::: "memory");
        __syncthreads();

        if (kt + 3 < NKT)
            load_stage(sbase + ((kt + 3) % STAGES) * STAGE_BYTES,
                       m0, n0, (kt + 3) * 64, tid);

        const uint32_t st = sbase + (kt % STAGES) * STAGE_BYTES;
        const uint32_t sa = st;
        const uint32_t sb = st + 16384;

        #pragma unroll
        for (int ks = 0; ks < 4; ++ks) {
            // ---- A fragments: 2 m-frags ----
            uint32_t af[2][4];
            #pragma unroll
            for (int mf = 0; mf < 2; ++mf) {
                int row = warp_m * 32 + mf * 16 + a_row_l;
                int c   = 2 * ks + a_chi;
                uint32_t off = (uint32_t)(row * 128 + ((c ^ (row & 7)) * 16));
                LDSM4(af[mf][0], af[mf][1], af[mf][2], af[mf][3], sa + off);
            }
            // ---- B fragments: 8 n-frags ----
            uint32_t bf[8][2];
            #pragma unroll
            for (int jp = 0; jp < 4; ++jp) {
                int row = warp_n * 64 + jp * 16 + b_row_l;
                int c   = 2 * ks + b_chi;
                uint32_t off = (uint32_t)(row * 128 + ((c ^ (row & 7)) * 16));
                LDSM4(bf[2*jp][0], bf[2*jp][1], bf[2*jp+1][0], bf[2*jp+1][1],
                      sb + off);
            }
            // ---- 16 HMMAs ----
            #pragma unroll
            for (int mf = 0; mf < 2; ++mf)
                #pragma unroll
                for (int j = 0; j < 8; ++j)
                    MMA_F16(acc[mf][j], af[mf], bf[j][0], bf[j][1]);
        }
    }

    // ---- epilogue: scatter accumulators to q/k/v head layout ----
    size_t obase;
    if (n0 < 8192)
        obase = (size_t)(n0 >> 7) * ((size_t)SEQ * 128);
    else if (n0 < 9216)
        obase = Q_ELEMS + (size_t)((n0 - 8192) >> 7) * ((size_t)SEQ * 128);
    else
        obase = Q_ELEMS + KV_ELEMS + (size_t)((n0 - 9216) >> 7) * ((size_t)SEQ * 128);

    const int rbase = m0 + warp_m * 32 + (lane >> 2);
    const int cbase = warp_n * 64 + (lane & 3) * 2;
    #pragma unroll
    for (int mf = 0; mf < 2; ++mf) {
        #pragma unroll
        for (int j = 0; j < 8; ++j) {
            int m = rbase + mf * 16;
            int c = cbase + j * 8;
            float* p0 = out + obase + (size_t)m * 128 + c;
            p0[0] = acc[mf][j][0];
            p0[1] = acc[mf][j][1];
            float* p1 = p0 + 8 * 128;
            p1[0] = acc[mf][j][2];
            p1[1] = acc[mf][j][3];
        }
    }
}

// ===================== host launcher =====================
extern "C" void kernel_launch(void* const* d_in, const int* in_sizes, int n_in,
                              void* d_out, int out_size) {
    const float* x = nullptr; const float* wq = nullptr;
    const float* wk = nullptr; const float* wv = nullptr;
    for (int i = 0; i < n_in; ++i) {
        long long sz = in_sizes[i];
        const float* p = (const float*)d_in[i];
        if (sz == (long long)SEQ * HID)       { if (!x) x = p; }
        else if (sz == (long long)HID * 8192) { if (!wq) wq = p; }
        else if (sz == (long long)HID * 1024) { if (!wk) wk = p; else if (!wv) wv = p; }
    }
    float* out = (float*)d_out;

    cudaFuncSetAttribute(qkv_gemm_kernel,
                         cudaFuncAttributeMaxDynamicSharedMemorySize, GEMM_SMEM);

    // 1) convert activations to fp16
    convert_x_kernel<<<2048, 256>>>(x);

    // 2) transpose + convert weights to fp16 B [NTOT][HID]
    dim3 tb(32, 8);
    transpose_half_kernel<<<dim3(8192 / 32, HID / 32), tb>>>(wq, 8192, 0);
    transpose_half_kernel<<<dim3(1024 / 32, HID / 32), tb>>>(wk, 1024, 8192);
    transpose_half_kernel<<<dim3(1024 / 32, HID / 32), tb>>>(wv, 1024, 9216);

    // 3) fp16 HMMA GEMM + fused q/k/v head scatter
    qkv_gemm_kernel<<<16 * 80, GEMM_THREADS, GEMM_SMEM>>>(out);
}

// round 5
// speedup vs baseline: 7.1743x; 1.0454x over previous
#include <cuda_runtime.h>
#include <cuda_fp16.h>
#include <cstdint>

// ===================== problem sizes =====================
#define SEQ   2048
#define HID   8192
#define NTOT  10240          // 8192 q + 1024 k + 1024 v
#define Q_ELEMS   ((size_t)64 * SEQ * 128)
#define KV_ELEMS  ((size_t)8  * SEQ * 128)

// ===================== scratch (fp16) =====================
__device__ unsigned short g_A[(size_t)SEQ * HID];
__device__ unsigned short g_B[(size_t)NTOT * HID];

// ===================== conversion kernels =====================
__global__ void convert_x_kernel(const float* __restrict__ x) {
    size_t n4 = (size_t)SEQ * HID / 4;
    for (size_t i = (size_t)blockIdx.x * blockDim.x + threadIdx.x;
         i < n4; i += (size_t)gridDim.x * blockDim.x) {
        float4 v = reinterpret_cast<const float4*>(x)[i];
        ushort4 h;
        h.x = __half_as_ushort(__float2half_rn(v.x));
        h.y = __half_as_ushort(__float2half_rn(v.y));
        h.z = __half_as_ushort(__float2half_rn(v.z));
        h.w = __half_as_ushort(__float2half_rn(v.w));
        reinterpret_cast<ushort4*>(g_A)[i] = h;
    }
}

// src: [HID rows][ncols] row-major fp32; writes B[n_off+n][k] = src[k][n] (fp16)
__global__ void transpose_half_kernel(const float* __restrict__ src,
                                      int ncols, int n_off) {
    __shared__ float tile[32][33];
    int c0b = blockIdx.x * 32;    // column (N) base
    int r0 = blockIdx.y * 32;     // row (K) base
    int tx = threadIdx.x, ty = threadIdx.y;
    #pragma unroll
    for (int i = 0; i < 32; i += 8)
        tile[ty + i][tx] = src[(size_t)(r0 + ty + i) * ncols + (c0b + tx)];
    __syncthreads();
    #pragma unroll
    for (int i = 0; i < 32; i += 8) {
        int n = n_off + c0b + ty + i;
        int k = r0 + tx;
        g_B[(size_t)n * HID + k] = __half_as_ushort(__float2half_rn(tile[tx][ty + i]));
    }
}

// ===================== GEMM kernel =====================
// CTA tile: 256M x 128N, BK=64. Warp grid 4x2, warp tile 64x64.
#define GEMM_THREADS 256
#define STAGES       4
#define A_BYTES      32768                   // 256 rows x 128B
#define B_BYTES      16384                   // 128 rows x 128B
#define STAGE_BYTES  (A_BYTES + B_BYTES)     // 48KB
#define GEMM_SMEM    (STAGES * STAGE_BYTES + 1024)

#define LDSM4(r0, r1, r2, r3, addr) \
    asm volatile("ldmatrix.sync.aligned.m8n8.x4.shared.b16 {%0,%1,%2,%3}, [%4];" \
        : "=r"(r0), "=r"(r1), "=r"(r2), "=r"(r3) : "r"(addr))

#define MMA_F16(d, a, b0, b1) \
    asm volatile("mma.sync.aligned.m16n8k16.row.col.f32.f16.f16.f32 " \
        "{%0,%1,%2,%3},{%4,%5,%6,%7},{%8,%9},{%0,%1,%2,%3};" \
        : "+f"((d)[0]), "+f"((d)[1]), "+f"((d)[2]), "+f"((d)[3]) \
        : "r"((a)[0]), "r"((a)[1]), "r"((a)[2]), "r"((a)[3]), "r"(b0), "r"(b1))

__device__ __forceinline__ uint32_t smem_to_u32(const void* p) {
    uint32_t addr;
    asm("{ .reg .u64 t; cvta.to.shared.u64 t, %1; cvt.u32.u64 %0, t; }"
        : "=r"(addr) : "l"(p));
    return addr;
}

// cp.async `nrows` x 128B into SW128-swizzled smem (8 chunks of 16B per row).
template <int NROWS>
__device__ __forceinline__ void cp_tile(uint32_t sdst, const unsigned short* gsrc,
                                        int row0, int k0, int tid) {
    const char* g = (const char*)(gsrc + (size_t)row0 * HID + k0);
    #pragma unroll
    for (int i = 0; i < NROWS * 8 / GEMM_THREADS; ++i) {
        int idx = i * GEMM_THREADS + tid;
        int r = idx >> 3;
        int c = idx & 7;
        uint32_t off = (uint32_t)(r * 128 + ((c ^ (r & 7)) * 16));
        const char* src = g + (size_t)r * (HID * 2) + c * 16;
        asm volatile("cp.async.cg.shared.global [%0], [%1], 16;"
                     :: "r"(sdst + off), "l"(src) : "memory");
    }
}

__device__ __forceinline__ void load_stage(uint32_t sstage, int m0, int n0,
                                           int k0, int tid) {
    cp_tile<256>(sstage,           g_A, m0, k0, tid);
    cp_tile<128>(sstage + A_BYTES, g_B, n0, k0, tid);
    asm volatile("cp.async.commit_group;" ::: "memory");
}

__global__ __launch_bounds__(GEMM_THREADS, 1)
void qkv_gemm_kernel(float* __restrict__ out) {
    extern __shared__ char smem_raw[];
    char* sm = (char*)(((uintptr_t)smem_raw + 1023) & ~(uintptr_t)1023);
    uint32_t sbase = smem_to_u32(sm);

    const int tid  = threadIdx.x;
    const int lane = tid & 31;
    const int wid  = tid >> 5;
    const int warp_m = wid & 3;    // 4 warps along M (64 rows each)
    const int warp_n = wid >> 2;   // 2 warps along N (64 cols each)

    const int m0 = (blockIdx.x & 7) << 8;         // 8 M-tiles of 256 (M-fastest)
    const int n0 = (int)(blockIdx.x >> 3) << 7;   // 80 N-tiles of 128

    float acc[4][8][4];
    #pragma unroll
    for (int i = 0; i < 4; ++i)
        #pragma unroll
        for (int j = 0; j < 8; ++j)
            #pragma unroll
            for (int r = 0; r < 4; ++r) acc[i][j][r] = 0.f;

    // ldmatrix lane-role decomposition
    const int a_row_l = lane & 15;
    const int a_chi   = lane >> 4;
    const int b_row_l = (lane & 7) + ((lane >> 4) & 1) * 8;
    const int b_chi   = (lane >> 3) & 1;

    // prologue: prefetch STAGES-1 stages
    load_stage(sbase + 0 * STAGE_BYTES, m0, n0, 0,   tid);
    load_stage(sbase + 1 * STAGE_BYTES, m0, n0, 64,  tid);
    load_stage(sbase + 2 * STAGE_BYTES, m0, n0, 128, tid);

    const int NKT = HID / 64;   // 128
    for (int kt = 0; kt < NKT; ++kt) {
        if (kt + 3 < NKT)
            asm volatile("cp.async.wait_group 2;" ::: "memory");
        else
            asm volatile("cp.async.wait_group 0;" ::: "memory");
        __syncthreads();

        if (kt + 3 < NKT)
            load_stage(sbase + ((kt + 3) % STAGES) * STAGE_BYTES,
                       m0, n0, (kt + 3) * 64, tid);

        const uint32_t st = sbase + (kt % STAGES) * STAGE_BYTES;
        const uint32_t sa = st;
        const uint32_t sb = st + A_BYTES;

        #pragma unroll
        for (int ks = 0; ks < 4; ++ks) {
            // ---- A fragments: 4 m-frags ----
            uint32_t af[4][4];
            #pragma unroll
            for (int mf = 0; mf < 4; ++mf) {
                int row = warp_m * 64 + mf * 16 + a_row_l;
                int c   = 2 * ks + a_chi;
                uint32_t off = (uint32_t)(row * 128 + ((c ^ (row & 7)) * 16));
                LDSM4(af[mf][0], af[mf][1], af[mf][2], af[mf][3], sa + off);
            }
            // ---- B fragments: 8 n-frags ----
            uint32_t bf[8][2];
            #pragma unroll
            for (int jp = 0; jp < 4; ++jp) {
                int row = warp_n * 64 + jp * 16 + b_row_l;
                int c   = 2 * ks + b_chi;
                uint32_t off = (uint32_t)(row * 128 + ((c ^ (row & 7)) * 16));
                LDSM4(bf[2*jp][0], bf[2*jp][1], bf[2*jp+1][0], bf[2*jp+1][1],
                      sb + off);
            }
            // ---- 32 HMMAs ----
            #pragma unroll
            for (int mf = 0; mf < 4; ++mf)
                #pragma unroll
                for (int j = 0; j < 8; ++j)
                    MMA_F16(acc[mf][j], af[mf], bf[j][0], bf[j][1]);
        }
    }

    // ---- epilogue: scatter accumulators to q/k/v head layout ----
    size_t obase;
    if (n0 < 8192)
        obase = (size_t)(n0 >> 7) * ((size_t)SEQ * 128);
    else if (n0 < 9216)
        obase = Q_ELEMS + (size_t)((n0 - 8192) >> 7) * ((size_t)SEQ * 128);
    else
        obase = Q_ELEMS + KV_ELEMS + (size_t)((n0 - 9216) >> 7) * ((size_t)SEQ * 128);

    const int rbase = m0 + warp_m * 64 + (lane >> 2);
    const int cbase = warp_n * 64 + (lane & 3) * 2;
    #pragma unroll
    for (int mf = 0; mf < 4; ++mf) {
        #pragma unroll
        for (int j = 0; j < 8; ++j) {
            int m = rbase + mf * 16;
            int c = cbase + j * 8;
            float* p0 = out + obase + (size_t)m * 128 + c;
            p0[0] = acc[mf][j][0];
            p0[1] = acc[mf][j][1];
            float* p1 = p0 + 8 * 128;
            p1[0] = acc[mf][j][2];
            p1[1] = acc[mf][j][3];
        }
    }
}

// ===================== host launcher =====================
extern "C" void kernel_launch(void* const* d_in, const int* in_sizes, int n_in,
                              void* d_out, int out_size) {
    const float* x = nullptr; const float* wq = nullptr;
    const float* wk = nullptr; const float* wv = nullptr;
    for (int i = 0; i < n_in; ++i) {
        long long sz = in_sizes[i];
        const float* p = (const float*)d_in[i];
        if (sz == (long long)SEQ * HID)       { if (!x) x = p; }
        else if (sz == (long long)HID * 8192) { if (!wq) wq = p; }
        else if (sz == (long long)HID * 1024) { if (!wk) wk = p; else if (!wv) wv = p; }
    }
    float* out = (float*)d_out;

    cudaFuncSetAttribute(qkv_gemm_kernel,
                         cudaFuncAttributeMaxDynamicSharedMemorySize, GEMM_SMEM);

    // 1) convert activations to fp16
    convert_x_kernel<<<2048, 256>>>(x);

    // 2) transpose + convert weights to fp16 B [NTOT][HID]
    dim3 tb(32, 8);
    transpose_half_kernel<<<dim3(8192 / 32, HID / 32), tb>>>(wq, 8192, 0);
    transpose_half_kernel<<<dim3(1024 / 32, HID / 32), tb>>>(wk, 1024, 8192);
    transpose_half_kernel<<<dim3(1024 / 32, HID / 32), tb>>>(wv, 1024, 9216);

    // 3) fp16 HMMA GEMM (256x128 CTA tile) + fused q/k/v head scatter
    qkv_gemm_kernel<<<8 * 80, GEMM_THREADS, GEMM_SMEM>>>(out);
}

// round 6
// speedup vs baseline: 7.9968x; 1.1146x over previous
#include <cuda_runtime.h>
#include <cuda_fp16.h>
#include <cstdint>

// ===================== problem sizes =====================
#define SEQ   2048
#define HID   8192
#define NTOT  10240          // 8192 q + 1024 k + 1024 v
#define Q_ELEMS   ((size_t)64 * SEQ * 128)
#define KV_ELEMS  ((size_t)8  * SEQ * 128)

// ===================== scratch (fp16) =====================
__device__ unsigned short g_A[(size_t)SEQ * HID];
__device__ unsigned short g_B[(size_t)NTOT * HID];

// ===================== conversion kernels =====================
__global__ void convert_x_kernel(const float* __restrict__ x) {
    size_t n4 = (size_t)SEQ * HID / 4;
    for (size_t i = (size_t)blockIdx.x * blockDim.x + threadIdx.x;
         i < n4; i += (size_t)gridDim.x * blockDim.x) {
        float4 v = reinterpret_cast<const float4*>(x)[i];
        ushort4 h;
        h.x = __half_as_ushort(__float2half_rn(v.x));
        h.y = __half_as_ushort(__float2half_rn(v.y));
        h.z = __half_as_ushort(__float2half_rn(v.z));
        h.w = __half_as_ushort(__float2half_rn(v.w));
        reinterpret_cast<ushort4*>(g_A)[i] = h;
    }
}

// One kernel for all three weights: global column n in [0,10240) picks the
// source tensor. Writes g_B[n][k] = w[k][n_local] (fp16).
__global__ void transpose_all_kernel(const float* __restrict__ wq,
                                     const float* __restrict__ wk,
                                     const float* __restrict__ wv) {
    __shared__ float tile[32][33];
    int n0 = blockIdx.x * 32;     // global output-row base (N)
    int r0 = blockIdx.y * 32;     // K base
    const float* src; int ncols; int nloc;
    if (n0 < 8192)      { src = wq; ncols = 8192; nloc = n0; }
    else if (n0 < 9216) { src = wk; ncols = 1024; nloc = n0 - 8192; }
    else                { src = wv; ncols = 1024; nloc = n0 - 9216; }
    int tx = threadIdx.x, ty = threadIdx.y;
    #pragma unroll
    for (int i = 0; i < 32; i += 8)
        tile[ty + i][tx] = src[(size_t)(r0 + ty + i) * ncols + (nloc + tx)];
    __syncthreads();
    #pragma unroll
    for (int i = 0; i < 32; i += 8) {
        int n = n0 + ty + i;
        int k = r0 + tx;
        g_B[(size_t)n * HID + k] = __half_as_ushort(__float2half_rn(tile[tx][ty + i]));
    }
}

// ===================== GEMM kernel =====================
// CTA tile: 128M x 128N, BK=64. 128 threads, warp grid 2x2, warp tile 64x64.
// 3 stages x 32KB = 96KB smem -> 2 CTAs/SM.
#define GEMM_THREADS 128
#define STAGES       3
#define A_BYTES      16384                   // 128 rows x 128B
#define B_BYTES      16384                   // 128 rows x 128B
#define STAGE_BYTES  (A_BYTES + B_BYTES)     // 32KB
#define GEMM_SMEM    (STAGES * STAGE_BYTES + 1024)

#define LDSM4(r0, r1, r2, r3, addr) \
    asm volatile("ldmatrix.sync.aligned.m8n8.x4.shared.b16 {%0,%1,%2,%3}, [%4];" \
        : "=r"(r0), "=r"(r1), "=r"(r2), "=r"(r3) : "r"(addr))

#define MMA_F16(d, a, b0, b1) \
    asm volatile("mma.sync.aligned.m16n8k16.row.col.f32.f16.f16.f32 " \
        "{%0,%1,%2,%3},{%4,%5,%6,%7},{%8,%9},{%0,%1,%2,%3};" \
        : "+f"((d)[0]), "+f"((d)[1]), "+f"((d)[2]), "+f"((d)[3]) \
        : "r"((a)[0]), "r"((a)[1]), "r"((a)[2]), "r"((a)[3]), "r"(b0), "r"(b1))

__device__ __forceinline__ uint32_t smem_to_u32(const void* p) {
    uint32_t addr;
    asm("{ .reg .u64 t; cvta.to.shared.u64 t, %1; cvt.u32.u64 %0, t; }"
        : "=r"(addr) : "l"(p));
    return addr;
}

// cp.async NROWS x 128B into SW128-swizzled smem (8 chunks of 16B per row).
template <int NROWS>
__device__ __forceinline__ void cp_tile(uint32_t sdst, const unsigned short* gsrc,
                                        int row0, int k0, int tid) {
    const char* g = (const char*)(gsrc + (size_t)row0 * HID + k0);
    #pragma unroll
    for (int i = 0; i < NROWS * 8 / GEMM_THREADS; ++i) {
        int idx = i * GEMM_THREADS + tid;
        int r = idx >> 3;
        int c = idx & 7;
        uint32_t off = (uint32_t)(r * 128 + ((c ^ (r & 7)) * 16));
        const char* src = g + (size_t)r * (HID * 2) + c * 16;
        asm volatile("cp.async.cg.shared.global [%0], [%1], 16;"
                     :: "r"(sdst + off), "l"(src) : "memory");
    }
}

__device__ __forceinline__ void load_stage(uint32_t sstage, int m0, int n0,
                                           int k0, int tid) {
    cp_tile<128>(sstage,           g_A, m0, k0, tid);
    cp_tile<128>(sstage + A_BYTES, g_B, n0, k0, tid);
    asm volatile("cp.async.commit_group;" ::: "memory");
}

__global__ __launch_bounds__(GEMM_THREADS, 2)
void qkv_gemm_kernel(float* __restrict__ out) {
    extern __shared__ char smem_raw[];
    char* sm = (char*)(((uintptr_t)smem_raw + 1023) & ~(uintptr_t)1023);
    uint32_t sbase = smem_to_u32(sm);

    const int tid  = threadIdx.x;
    const int lane = tid & 31;
    const int wid  = tid >> 5;
    const int warp_m = wid & 1;    // 2 warps along M (64 rows each)
    const int warp_n = wid >> 1;   // 2 warps along N (64 cols each)

    const int m0 = (blockIdx.x & 15) << 7;        // 16 M-tiles (M-fastest)
    const int n0 = (int)(blockIdx.x >> 4) << 7;   // 80 N-tiles

    float acc[4][8][4];
    #pragma unroll
    for (int i = 0; i < 4; ++i)
        #pragma unroll
        for (int j = 0; j < 8; ++j)
            #pragma unroll
            for (int r = 0; r < 4; ++r) acc[i][j][r] = 0.f;

    // ldmatrix lane-role decomposition
    const int a_row_l = lane & 15;
    const int a_chi   = lane >> 4;
    const int b_row_l = (lane & 7) + ((lane >> 4) & 1) * 8;
    const int b_chi   = (lane >> 3) & 1;

    // prologue: prefetch STAGES-1 stages
    load_stage(sbase + 0 * STAGE_BYTES, m0, n0, 0,  tid);
    load_stage(sbase + 1 * STAGE_BYTES, m0, n0, 64, tid);

    const int NKT = HID / 64;   // 128
    for (int kt = 0; kt < NKT; ++kt) {
        if (kt + 2 < NKT)
            asm volatile("cp.async.wait_group 1;" ::: "memory");
        else
            asm volatile("cp.async.wait_group 0;" ::: "memory");
        __syncthreads();

        if (kt + 2 < NKT)
            load_stage(sbase + ((kt + 2) % STAGES) * STAGE_BYTES,
                       m0, n0, (kt + 2) * 64, tid);

        const uint32_t st = sbase + (kt % STAGES) * STAGE_BYTES;
        const uint32_t sa = st;
        const uint32_t sb = st + A_BYTES;

        #pragma unroll
        for (int ks = 0; ks < 4; ++ks) {
            // ---- A fragments: 4 m-frags ----
            uint32_t af[4][4];
            #pragma unroll
            for (int mf = 0; mf < 4; ++mf) {
                int row = warp_m * 64 + mf * 16 + a_row_l;
                int c   = 2 * ks + a_chi;
                uint32_t off = (uint32_t)(row * 128 + ((c ^ (row & 7)) * 16));
                LDSM4(af[mf][0], af[mf][1], af[mf][2], af[mf][3], sa + off);
            }
            // ---- B fragments: 8 n-frags ----
            uint32_t bf[8][2];
            #pragma unroll
            for (int jp = 0; jp < 4; ++jp) {
                int row = warp_n * 64 + jp * 16 + b_row_l;
                int c   = 2 * ks + b_chi;
                uint32_t off = (uint32_t)(row * 128 + ((c ^ (row & 7)) * 16));
                LDSM4(bf[2*jp][0], bf[2*jp][1], bf[2*jp+1][0], bf[2*jp+1][1],
                      sb + off);
            }
            // ---- 32 HMMAs ----
            #pragma unroll
            for (int mf = 0; mf < 4; ++mf)
                #pragma unroll
                for (int j = 0; j < 8; ++j)
                    MMA_F16(acc[mf][j], af[mf], bf[j][0], bf[j][1]);
        }
    }

    // ---- epilogue: scatter accumulators to q/k/v head layout ----
    size_t obase;
    if (n0 < 8192)
        obase = (size_t)(n0 >> 7) * ((size_t)SEQ * 128);
    else if (n0 < 9216)
        obase = Q_ELEMS + (size_t)((n0 - 8192) >> 7) * ((size_t)SEQ * 128);
    else
        obase = Q_ELEMS + KV_ELEMS + (size_t)((n0 - 9216) >> 7) * ((size_t)SEQ * 128);

    const int rbase = m0 + warp_m * 64 + (lane >> 2);
    const int cbase = warp_n * 64 + (lane & 3) * 2;
    #pragma unroll
    for (int mf = 0; mf < 4; ++mf) {
        #pragma unroll
        for (int j = 0; j < 8; ++j) {
            int m = rbase + mf * 16;
            int c = cbase + j * 8;
            float* p0 = out + obase + (size_t)m * 128 + c;
            p0[0] = acc[mf][j][0];
            p0[1] = acc[mf][j][1];
            float* p1 = p0 + 8 * 128;
            p1[0] = acc[mf][j][2];
            p1[1] = acc[mf][j][3];
        }
    }
}

// ===================== host launcher =====================
extern "C" void kernel_launch(void* const* d_in, const int* in_sizes, int n_in,
                              void* d_out, int out_size) {
    const float* x = nullptr; const float* wq = nullptr;
    const float* wk = nullptr; const float* wv = nullptr;
    for (int i = 0; i < n_in; ++i) {
        long long sz = in_sizes[i];
        const float* p = (const float*)d_in[i];
        if (sz == (long long)SEQ * HID)       { if (!x) x = p; }
        else if (sz == (long long)HID * 8192) { if (!wq) wq = p; }
        else if (sz == (long long)HID * 1024) { if (!wk) wk = p; else if (!wv) wv = p; }
    }
    float* out = (float*)d_out;

    cudaFuncSetAttribute(qkv_gemm_kernel,
                         cudaFuncAttributeMaxDynamicSharedMemorySize, GEMM_SMEM);

    // 1) convert activations to fp16
    convert_x_kernel<<<2048, 256>>>(x);

    // 2) transpose + convert all weights to fp16 B [NTOT][HID] (one launch)
    dim3 tb(32, 8);
    transpose_all_kernel<<<dim3(NTOT / 32, HID / 32), tb>>>(wq, wk, wv);

    // 3) fp16 HMMA GEMM (128x128 CTA tile, 2 CTAs/SM) + fused q/k/v scatter
    qkv_gemm_kernel<<<16 * 80, GEMM_THREADS, GEMM_SMEM>>>(out);
}

// round 7
// speedup vs baseline: 8.3351x; 1.0423x over previous
#include <cuda_runtime.h>
#include <cuda_fp16.h>
#include <cstdint>

// ===================== problem sizes =====================
#define SEQ   2048
#define HID   8192
#define NTOT  10240          // 8192 q + 1024 k + 1024 v
#define Q_ELEMS   ((size_t)64 * SEQ * 128)
#define KV_ELEMS  ((size_t)8  * SEQ * 128)

// ===================== scratch (fp16) =====================
__device__ unsigned short g_A[(size_t)SEQ * HID];     // [SEQ][HID]  (M-major)
__device__ unsigned short g_B[(size_t)HID * NTOT];    // [HID][NTOT] (K-major!)

// ===================== conversion kernels =====================
__global__ void convert_x_kernel(const float* __restrict__ x) {
    size_t n4 = (size_t)SEQ * HID / 4;
    for (size_t i = (size_t)blockIdx.x * blockDim.x + threadIdx.x;
         i < n4; i += (size_t)gridDim.x * blockDim.x) {
        float4 v = reinterpret_cast<const float4*>(x)[i];
        ushort4 h;
        h.x = __half_as_ushort(__float2half_rn(v.x));
        h.y = __half_as_ushort(__float2half_rn(v.y));
        h.z = __half_as_ushort(__float2half_rn(v.z));
        h.w = __half_as_ushort(__float2half_rn(v.w));
        reinterpret_cast<ushort4*>(g_A)[i] = h;
    }
}

// Streaming convert: g_B[k][n_off + n] = fp16(src[k][n]); both sides coalesced.
__global__ void convert_w_kernel(const float* __restrict__ src,
                                 int ncols, int n_off) {
    size_t n4 = (size_t)HID * ncols / 4;
    for (size_t i = (size_t)blockIdx.x * blockDim.x + threadIdx.x;
         i < n4; i += (size_t)gridDim.x * blockDim.x) {
        float4 v = reinterpret_cast<const float4*>(src)[i];
        ushort4 h;
        h.x = __half_as_ushort(__float2half_rn(v.x));
        h.y = __half_as_ushort(__float2half_rn(v.y));
        h.z = __half_as_ushort(__float2half_rn(v.z));
        h.w = __half_as_ushort(__float2half_rn(v.w));
        size_t e = i * 4;
        size_t k = e / (size_t)ncols;
        size_t n = e - k * (size_t)ncols;
        *reinterpret_cast<ushort4*>(&g_B[k * NTOT + n_off + n]) = h;
    }
}

// ===================== GEMM kernel =====================
// CTA tile: 128M x 128N, BK=64. 128 threads, warp grid 2x2, warp tile 64x64.
// A stage: 128 rows(m) x 128B(k).  B stage: 64 rows(k) x 256B(n).
// 3 stages x 32KB = 96KB smem -> 2 CTAs/SM.
#define GEMM_THREADS 128
#define STAGES       3
#define A_BYTES      16384
#define B_BYTES      16384
#define STAGE_BYTES  (A_BYTES + B_BYTES)     // 32KB
#define GEMM_SMEM    (STAGES * STAGE_BYTES + 1024)

#define LDSM4(r0, r1, r2, r3, addr) \
    asm volatile("ldmatrix.sync.aligned.m8n8.x4.shared.b16 {%0,%1,%2,%3}, [%4];" \
        : "=r"(r0), "=r"(r1), "=r"(r2), "=r"(r3) : "r"(addr))

#define LDSM4T(r0, r1, r2, r3, addr) \
    asm volatile("ldmatrix.sync.aligned.m8n8.x4.trans.shared.b16 {%0,%1,%2,%3}, [%4];" \
        : "=r"(r0), "=r"(r1), "=r"(r2), "=r"(r3) : "r"(addr))

#define MMA_F16(d, a, b0, b1) \
    asm volatile("mma.sync.aligned.m16n8k16.row.col.f32.f16.f16.f32 " \
        "{%0,%1,%2,%3},{%4,%5,%6,%7},{%8,%9},{%0,%1,%2,%3};" \
        : "+f"((d)[0]), "+f"((d)[1]), "+f"((d)[2]), "+f"((d)[3]) \
        : "r"((a)[0]), "r"((a)[1]), "r"((a)[2]), "r"((a)[3]), "r"(b0), "r"(b1))

__device__ __forceinline__ uint32_t smem_to_u32(const void* p) {
    uint32_t addr;
    asm("{ .reg .u64 t; cvta.to.shared.u64 t, %1; cvt.u32.u64 %0, t; }"
        : "=r"(addr) : "l"(p));
    return addr;
}

// A tile: 128 rows x 128B, SW128-swizzled (8 chunks of 16B per row).
__device__ __forceinline__ void cp_tile_a(uint32_t sdst, int m0, int k0, int tid) {
    const char* g = (const char*)(g_A + (size_t)m0 * HID + k0);
    #pragma unroll
    for (int i = 0; i < 8; ++i) {
        int idx = i * GEMM_THREADS + tid;   // 0..1023
        int r = idx >> 3;
        int c = idx & 7;
        uint32_t off = (uint32_t)(r * 128 + ((c ^ (r & 7)) * 16));
        const char* src = g + (size_t)r * (HID * 2) + c * 16;
        asm volatile("cp.async.cg.shared.global [%0], [%1], 16;"
                     :: "r"(sdst + off), "l"(src) : "memory");
    }
}

// B tile: 64 rows(k) x 256B(n), per-128B-half XOR swizzle keyed on k-row.
__device__ __forceinline__ void cp_tile_b(uint32_t sdst, int n0, int k0, int tid) {
    const char* g = (const char*)(g_B + (size_t)k0 * NTOT + n0);
    #pragma unroll
    for (int i = 0; i < 8; ++i) {
        int idx = i * GEMM_THREADS + tid;   // 0..1023
        int r = idx >> 4;                   // k row 0..63
        int c = idx & 15;                   // 16B chunk 0..15
        uint32_t off = (uint32_t)(r * 256 + (c & 8) * 16
                                  + (((c & 7) ^ (r & 7)) * 16));
        const char* src = g + (size_t)r * (NTOT * 2) + c * 16;
        asm volatile("cp.async.cg.shared.global [%0], [%1], 16;"
                     :: "r"(sdst + off), "l"(src) : "memory");
    }
}

__device__ __forceinline__ void load_stage(uint32_t sstage, int m0, int n0,
                                           int k0, int tid) {
    cp_tile_a(sstage,           m0, k0, tid);
    cp_tile_b(sstage + A_BYTES, n0, k0, tid);
    asm volatile("cp.async.commit_group;" ::: "memory");
}

__global__ __launch_bounds__(GEMM_THREADS, 2)
void qkv_gemm_kernel(float* __restrict__ out) {
    extern __shared__ char smem_raw[];
    char* sm = (char*)(((uintptr_t)smem_raw + 1023) & ~(uintptr_t)1023);
    uint32_t sbase = smem_to_u32(sm);

    const int tid  = threadIdx.x;
    const int lane = tid & 31;
    const int wid  = tid >> 5;
    const int warp_m = wid & 1;    // 2 warps along M (64 rows each)
    const int warp_n = wid >> 1;   // 2 warps along N (64 cols each)

    const int m0 = (blockIdx.x & 15) << 7;        // 16 M-tiles (M-fastest)
    const int n0 = (int)(blockIdx.x >> 4) << 7;   // 80 N-tiles

    float acc[4][8][4];
    #pragma unroll
    for (int i = 0; i < 4; ++i)
        #pragma unroll
        for (int j = 0; j < 8; ++j)
            #pragma unroll
            for (int r = 0; r < 4; ++r) acc[i][j][r] = 0.f;

    // A ldmatrix lane roles (non-trans, [M][K] tile, 128B rows)
    const int a_row_l = lane & 15;
    const int a_chi   = lane >> 4;
    // B ldmatrix.trans lane roles ([K][N] tile, 256B rows):
    //   k-in-16 = (lane&7) + ((lane>>3)&1)*8 ; n 16B chunk += (lane>>4)
    const int b_krow  = (lane & 7) + ((lane >> 3) & 1) * 8;
    const int b_nchi  = lane >> 4;              // 0/1 -> n8 group within n16

    // prologue: prefetch STAGES-1 stages
    load_stage(sbase + 0 * STAGE_BYTES, m0, n0, 0,  tid);
    load_stage(sbase + 1 * STAGE_BYTES, m0, n0, 64, tid);

    const int NKT = HID / 64;   // 128
    for (int kt = 0; kt < NKT; ++kt) {
        if (kt + 2 < NKT)
            asm volatile("cp.async.wait_group 1;" ::: "memory");
        else
            asm volatile("cp.async.wait_group 0;" ::: "memory");
        __syncthreads();

        if (kt + 2 < NKT)
            load_stage(sbase + ((kt + 2) % STAGES) * STAGE_BYTES,
                       m0, n0, (kt + 2) * 64, tid);

        const uint32_t st = sbase + (kt % STAGES) * STAGE_BYTES;
        const uint32_t sa = st;
        const uint32_t sb = st + A_BYTES;

        #pragma unroll
        for (int ks = 0; ks < 4; ++ks) {
            // ---- A fragments: 4 m-frags (non-trans) ----
            uint32_t af[4][4];
            #pragma unroll
            for (int mf = 0; mf < 4; ++mf) {
                int row = warp_m * 64 + mf * 16 + a_row_l;
                int c   = 2 * ks + a_chi;
                uint32_t off = (uint32_t)(row * 128 + ((c ^ (row & 7)) * 16));
                LDSM4(af[mf][0], af[mf][1], af[mf][2], af[mf][3], sa + off);
            }
            // ---- B fragments: 8 n-frags via ldsm.trans on [K][N] tile ----
            uint32_t bf[8][2];
            #pragma unroll
            for (int jp = 0; jp < 4; ++jp) {
                int krow = ks * 16 + b_krow;              // k row 0..63
                int nb   = warp_n * 128 + jp * 32 + b_nchi * 16;  // byte in row
                uint32_t off = (uint32_t)(krow * 256 + (nb & 128)
                               + ((((nb >> 4) & 7) ^ (krow & 7)) * 16));
                LDSM4T(bf[2*jp][0], bf[2*jp][1], bf[2*jp+1][0], bf[2*jp+1][1],
                       sb + off);
            }
            // ---- 32 HMMAs ----
            #pragma unroll
            for (int mf = 0; mf < 4; ++mf)
                #pragma unroll
                for (int j = 0; j < 8; ++j)
                    MMA_F16(acc[mf][j], af[mf], bf[j][0], bf[j][1]);
        }
    }

    // ---- epilogue: scatter accumulators to q/k/v head layout ----
    size_t obase;
    if (n0 < 8192)
        obase = (size_t)(n0 >> 7) * ((size_t)SEQ * 128);
    else if (n0 < 9216)
        obase = Q_ELEMS + (size_t)((n0 - 8192) >> 7) * ((size_t)SEQ * 128);
    else
        obase = Q_ELEMS + KV_ELEMS + (size_t)((n0 - 9216) >> 7) * ((size_t)SEQ * 128);

    const int rbase = m0 + warp_m * 64 + (lane >> 2);
    const int cbase = warp_n * 64 + (lane & 3) * 2;
    #pragma unroll
    for (int mf = 0; mf < 4; ++mf) {
        #pragma unroll
        for (int j = 0; j < 8; ++j) {
            int m = rbase + mf * 16;
            int c = cbase + j * 8;
            float* p0 = out + obase + (size_t)m * 128 + c;
            p0[0] = acc[mf][j][0];
            p0[1] = acc[mf][j][1];
            float* p1 = p0 + 8 * 128;
            p1[0] = acc[mf][j][2];
            p1[1] = acc[mf][j][3];
        }
    }
}

// ===================== host launcher =====================
extern "C" void kernel_launch(void* const* d_in, const int* in_sizes, int n_in,
                              void* d_out, int out_size) {
    const float* x = nullptr; const float* wq = nullptr;
    const float* wk = nullptr; const float* wv = nullptr;
    for (int i = 0; i < n_in; ++i) {
        long long sz = in_sizes[i];
        const float* p = (const float*)d_in[i];
        if (sz == (long long)SEQ * HID)       { if (!x) x = p; }
        else if (sz == (long long)HID * 8192) { if (!wq) wq = p; }
        else if (sz == (long long)HID * 1024) { if (!wk) wk = p; else if (!wv) wv = p; }
    }
    float* out = (float*)d_out;

    cudaFuncSetAttribute(qkv_gemm_kernel,
                         cudaFuncAttributeMaxDynamicSharedMemorySize, GEMM_SMEM);

    // 1) convert activations to fp16 (streaming)
    convert_x_kernel<<<2048, 256>>>(x);

    // 2) streaming convert weights into K-major g_B [HID][NTOT] (no transpose)
    convert_w_kernel<<<4096, 256>>>(wq, 8192, 0);
    convert_w_kernel<<<1024, 256>>>(wk, 1024, 8192);
    convert_w_kernel<<<1024, 256>>>(wv, 1024, 9216);

    // 3) fp16 HMMA GEMM (128x128 tile, 2 CTAs/SM, ldsm.trans B) + q/k/v scatter
    qkv_gemm_kernel<<<16 * 80, GEMM_THREADS, GEMM_SMEM>>>(out);
}

// round 8
// speedup vs baseline: 8.8493x; 1.0617x over previous
#include <cuda_runtime.h>
#include <cuda_fp16.h>
#include <cstdint>

// ===================== problem sizes =====================
#define SEQ   2048
#define HID   8192
#define NTOT  10240          // 8192 q + 1024 k + 1024 v
#define Q_ELEMS   ((size_t)64 * SEQ * 128)
#define KV_ELEMS  ((size_t)8  * SEQ * 128)

// ===================== scratch (fp16) =====================
__device__ unsigned short g_A[(size_t)SEQ * HID];     // [SEQ][HID]  (M-major)
__device__ unsigned short g_B[(size_t)HID * NTOT];    // [HID][NTOT] (K-major)

// ===================== conversion kernels =====================
__global__ void convert_x_kernel(const float* __restrict__ x) {
    size_t n4 = (size_t)SEQ * HID / 4;
    for (size_t i = (size_t)blockIdx.x * blockDim.x + threadIdx.x;
         i < n4; i += (size_t)gridDim.x * blockDim.x) {
        float4 v = reinterpret_cast<const float4*>(x)[i];
        ushort4 h;
        h.x = __half_as_ushort(__float2half_rn(v.x));
        h.y = __half_as_ushort(__float2half_rn(v.y));
        h.z = __half_as_ushort(__float2half_rn(v.z));
        h.w = __half_as_ushort(__float2half_rn(v.w));
        reinterpret_cast<ushort4*>(g_A)[i] = h;
    }
}

// Div-free streaming convert: one k-row per blockIdx.y.
// g_B[k][n_off + n] = fp16(src[k][n]); both sides coalesced.
__global__ void convert_w_kernel(const float* __restrict__ src,
                                 int ncols, int n_off) {
    int k = blockIdx.y;
    int n4 = blockIdx.x * blockDim.x + threadIdx.x;   // float4 index in row
    const float4* s = reinterpret_cast<const float4*>(src + (size_t)k * ncols);
    float4 v = s[n4];
    ushort4 h;
    h.x = __half_as_ushort(__float2half_rn(v.x));
    h.y = __half_as_ushort(__float2half_rn(v.y));
    h.z = __half_as_ushort(__float2half_rn(v.z));
    h.w = __half_as_ushort(__float2half_rn(v.w));
    *reinterpret_cast<ushort4*>(&g_B[(size_t)k * NTOT + n_off + n4 * 4]) = h;
}

// ===================== GEMM kernel =====================
// CTA tile: 128M x 64N, BK=64. 128 threads, warp grid 2x2, warp tile 64x32.
// A stage: 128 rows(m) x 128B(k). B stage: 64 rows(k) x 128B(n).
// 3 stages x 24KB = 72KB smem -> 3 CTAs/SM (219KB, 12 warps/SM).
#define GEMM_THREADS 128
#define STAGES       3
#define A_BYTES      16384
#define B_BYTES      8192
#define STAGE_BYTES  (A_BYTES + B_BYTES)     // 24KB
#define GEMM_SMEM    (STAGES * STAGE_BYTES + 1024)

#define LDSM4(r0, r1, r2, r3, addr) \
    asm volatile("ldmatrix.sync.aligned.m8n8.x4.shared.b16 {%0,%1,%2,%3}, [%4];" \
        : "=r"(r0), "=r"(r1), "=r"(r2), "=r"(r3) : "r"(addr))

#define LDSM4T(r0, r1, r2, r3, addr) \
    asm volatile("ldmatrix.sync.aligned.m8n8.x4.trans.shared.b16 {%0,%1,%2,%3}, [%4];" \
        : "=r"(r0), "=r"(r1), "=r"(r2), "=r"(r3) : "r"(addr))

#define MMA_F16(d, a, b0, b1) \
    asm volatile("mma.sync.aligned.m16n8k16.row.col.f32.f16.f16.f32 " \
        "{%0,%1,%2,%3},{%4,%5,%6,%7},{%8,%9},{%0,%1,%2,%3};" \
        : "+f"((d)[0]), "+f"((d)[1]), "+f"((d)[2]), "+f"((d)[3]) \
        : "r"((a)[0]), "r"((a)[1]), "r"((a)[2]), "r"((a)[3]), "r"(b0), "r"(b1))

__device__ __forceinline__ uint32_t smem_to_u32(const void* p) {
    uint32_t addr;
    asm("{ .reg .u64 t; cvta.to.shared.u64 t, %1; cvt.u32.u64 %0, t; }"
        : "=r"(addr) : "l"(p));
    return addr;
}

// A tile: 128 rows x 128B, SW128-swizzled (8 chunks of 16B per row).
__device__ __forceinline__ void cp_tile_a(uint32_t sdst, int m0, int k0, int tid) {
    const char* g = (const char*)(g_A + (size_t)m0 * HID + k0);
    #pragma unroll
    for (int i = 0; i < 8; ++i) {
        int idx = i * GEMM_THREADS + tid;   // 0..1023
        int r = idx >> 3;
        int c = idx & 7;
        uint32_t off = (uint32_t)(r * 128 + ((c ^ (r & 7)) * 16));
        const char* src = g + (size_t)r * (HID * 2) + c * 16;
        asm volatile("cp.async.cg.shared.global [%0], [%1], 16;"
                     :: "r"(sdst + off), "l"(src) : "memory");
    }
}

// B tile: 64 rows(k) x 128B(n=64 fp16), SW128 swizzle keyed on k-row.
__device__ __forceinline__ void cp_tile_b(uint32_t sdst, int n0, int k0, int tid) {
    const char* g = (const char*)(g_B + (size_t)k0 * NTOT + n0);
    #pragma unroll
    for (int i = 0; i < 4; ++i) {
        int idx = i * GEMM_THREADS + tid;   // 0..511
        int r = idx >> 3;                   // k row 0..63
        int c = idx & 7;                    // 16B chunk 0..7
        uint32_t off = (uint32_t)(r * 128 + ((c ^ (r & 7)) * 16));
        const char* src = g + (size_t)r * (NTOT * 2) + c * 16;
        asm volatile("cp.async.cg.shared.global [%0], [%1], 16;"
                     :: "r"(sdst + off), "l"(src) : "memory");
    }
}

__device__ __forceinline__ void load_stage(uint32_t sstage, int m0, int n0,
                                           int k0, int tid) {
    cp_tile_a(sstage,           m0, k0, tid);
    cp_tile_b(sstage + A_BYTES, n0, k0, tid);
    asm volatile("cp.async.commit_group;" ::: "memory");
}

__global__ __launch_bounds__(GEMM_THREADS, 3)
void qkv_gemm_kernel(float* __restrict__ out) {
    extern __shared__ char smem_raw[];
    char* sm = (char*)(((uintptr_t)smem_raw + 1023) & ~(uintptr_t)1023);
    uint32_t sbase = smem_to_u32(sm);

    const int tid  = threadIdx.x;
    const int lane = tid & 31;
    const int wid  = tid >> 5;
    const int warp_m = wid & 1;    // 2 warps along M (64 rows each)
    const int warp_n = wid >> 1;   // 2 warps along N (32 cols each)

    const int m0 = (blockIdx.x & 15) << 7;        // 16 M-tiles (M-fastest)
    const int n0 = (int)(blockIdx.x >> 4) << 6;   // 160 N-tiles of 64

    float acc[4][4][4];
    #pragma unroll
    for (int i = 0; i < 4; ++i)
        #pragma unroll
        for (int j = 0; j < 4; ++j)
            #pragma unroll
            for (int r = 0; r < 4; ++r) acc[i][j][r] = 0.f;

    // A ldmatrix lane roles (non-trans, [M][K] tile, 128B rows)
    const int a_row_l = lane & 15;
    const int a_chi   = lane >> 4;
    // B ldmatrix.trans lane roles ([K][N] tile, 128B rows)
    const int b_krow  = (lane & 7) + ((lane >> 3) & 1) * 8;
    const int b_nchi  = lane >> 4;               // 0/1 -> n8 group within n16

    // prologue: prefetch STAGES-1 stages
    load_stage(sbase + 0 * STAGE_BYTES, m0, n0, 0,  tid);
    load_stage(sbase + 1 * STAGE_BYTES, m0, n0, 64, tid);

    const int NKT = HID / 64;   // 128
    for (int kt = 0; kt < NKT; ++kt) {
        if (kt + 2 < NKT)
            asm volatile("cp.async.wait_group 1;" ::: "memory");
        else
            asm volatile("cp.async.wait_group 0;" ::: "memory");
        __syncthreads();

        if (kt + 2 < NKT)
            load_stage(sbase + ((kt + 2) % STAGES) * STAGE_BYTES,
                       m0, n0, (kt + 2) * 64, tid);

        const uint32_t st = sbase + (kt % STAGES) * STAGE_BYTES;
        const uint32_t sa = st;
        const uint32_t sb = st + A_BYTES;

        #pragma unroll
        for (int ks = 0; ks < 4; ++ks) {
            // ---- A fragments: 4 m-frags (non-trans) ----
            uint32_t af[4][4];
            #pragma unroll
            for (int mf = 0; mf < 4; ++mf) {
                int row = warp_m * 64 + mf * 16 + a_row_l;
                int c   = 2 * ks + a_chi;
                uint32_t off = (uint32_t)(row * 128 + ((c ^ (row & 7)) * 16));
                LDSM4(af[mf][0], af[mf][1], af[mf][2], af[mf][3], sa + off);
            }
            // ---- B fragments: 4 n8-frags via 2 ldsm.trans on [K][N] tile ----
            uint32_t bf[4][2];
            #pragma unroll
            for (int jp = 0; jp < 2; ++jp) {
                int krow = ks * 16 + b_krow;                 // k row 0..63
                int nb   = warp_n * 64 + jp * 32 + b_nchi * 16;  // byte in row
                uint32_t off = (uint32_t)(krow * 128
                               + ((((nb >> 4) & 7) ^ (krow & 7)) * 16));
                LDSM4T(bf[2*jp][0], bf[2*jp][1], bf[2*jp+1][0], bf[2*jp+1][1],
                       sb + off);
            }
            // ---- 16 HMMAs ----
            #pragma unroll
            for (int mf = 0; mf < 4; ++mf)
                #pragma unroll
                for (int j = 0; j < 4; ++j)
                    MMA_F16(acc[mf][j], af[mf], bf[j][0], bf[j][1]);
        }
    }

    // ---- epilogue: scatter accumulators to q/k/v head layout ----
    // N-tile (64 cols) = half of one 128-wide head; head index = n0>>7.
    size_t obase;
    if (n0 < 8192)
        obase = (size_t)(n0 >> 7) * ((size_t)SEQ * 128);
    else if (n0 < 9216)
        obase = Q_ELEMS + (size_t)((n0 - 8192) >> 7) * ((size_t)SEQ * 128);
    else
        obase = Q_ELEMS + KV_ELEMS + (size_t)((n0 - 9216) >> 7) * ((size_t)SEQ * 128);
    const int chalf = n0 & 64;   // which half of the head

    const int rbase = m0 + warp_m * 64 + (lane >> 2);
    const int cbase = chalf + warp_n * 32 + (lane & 3) * 2;
    #pragma unroll
    for (int mf = 0; mf < 4; ++mf) {
        #pragma unroll
        for (int j = 0; j < 4; ++j) {
            int m = rbase + mf * 16;
            int c = cbase + j * 8;
            float* p0 = out + obase + (size_t)m * 128 + c;
            p0[0] = acc[mf][j][0];
            p0[1] = acc[mf][j][1];
            float* p1 = p0 + 8 * 128;
            p1[0] = acc[mf][j][2];
            p1[1] = acc[mf][j][3];
        }
    }
}

// ===================== host launcher =====================
extern "C" void kernel_launch(void* const* d_in, const int* in_sizes, int n_in,
                              void* d_out, int out_size) {
    const float* x = nullptr; const float* wq = nullptr;
    const float* wk = nullptr; const float* wv = nullptr;
    for (int i = 0; i < n_in; ++i) {
        long long sz = in_sizes[i];
        const float* p = (const float*)d_in[i];
        if (sz == (long long)SEQ * HID)       { if (!x) x = p; }
        else if (sz == (long long)HID * 8192) { if (!wq) wq = p; }
        else if (sz == (long long)HID * 1024) { if (!wk) wk = p; else if (!wv) wv = p; }
    }
    float* out = (float*)d_out;

    cudaFuncSetAttribute(qkv_gemm_kernel,
                         cudaFuncAttributeMaxDynamicSharedMemorySize, GEMM_SMEM);

    // 1) convert activations to fp16 (streaming)
    convert_x_kernel<<<2048, 256>>>(x);

    // 2) div-free streaming convert weights into K-major g_B [HID][NTOT]
    convert_w_kernel<<<dim3(8192 / 1024, HID), 256>>>(wq, 8192, 0);
    convert_w_kernel<<<dim3(1024 / 1024, HID), 256>>>(wk, 1024, 8192);
    convert_w_kernel<<<dim3(1024 / 1024, HID), 256>>>(wv, 1024, 9216);

    // 3) fp16 HMMA GEMM (128x64 tile, 3 CTAs/SM) + fused q/k/v head scatter
    qkv_gemm_kernel<<<16 * 160, GEMM_THREADS, GEMM_SMEM>>>(out);
}